// round 16
// baseline (speedup 1.0000x reference)
#include <cuda_runtime.h>
#include <cuda_bf16.h>
#include <cstdint>
#include <cstddef>

#define TT   100
#define BB   1024
#define NHD  128
#define NGATE 512
#define NIC  268
#define NBOT 256
#define NPC  256
#define NHDC 12
#define TB   (TT * BB)

// ---------------------------------------------------------------------------
// device scratch
// ---------------------------------------------------------------------------
__device__ float g_c0[BB * NHD];
// h history pre-split bf16: slot 0 = h0, slot t+1 = h_t
__device__ __nv_bfloat16 g_hh[(size_t)(TT + 1) * BB * NHD];
__device__ __nv_bfloat16 g_hl[(size_t)(TT + 1) * BB * NHD];
__device__ __nv_bfloat16 g_bwh[NHD * NBOT], g_bwl[NHD * NBOT];
__device__ __nv_bfloat16 g_pwh[NBOT * NPC], g_pwl[NBOT * NPC];
__device__ __nv_bfloat16 g_hdh[NBOT * 16], g_hdl[NBOT * 16];
// per-row-tile flags: g_flag[rt*4 + cg], monotone epochs across replays
__device__ unsigned g_flag[32 * 32];

__device__ __forceinline__ float sigm(float v) { return 1.0f / (1.0f + __expf(-v)); }
__device__ __forceinline__ float tanh_fast(float v) {
    return 1.0f - 2.0f / (__expf(2.0f * v) + 1.0f);
}
__device__ __forceinline__ void split2(float v, __nv_bfloat16& hi, __nv_bfloat16& lo) {
    hi = __float2bfloat16(v);
    lo = __float2bfloat16(v - __bfloat162float(hi));
}
__device__ __forceinline__ uint32_t smem_u32(const void* p) {
    uint32_t a;
    asm("{ .reg .u64 t; cvta.to.shared.u64 t, %1; cvt.u32.u64 %0, t; }" : "=r"(a) : "l"(p));
    return a;
}
__device__ __forceinline__ unsigned ld_acq(const unsigned* p) {
    unsigned v;
    asm volatile("ld.acquire.gpu.global.u32 %0, [%1];" : "=r"(v) : "l"(p) : "memory");
    return v;
}
__device__ __forceinline__ void st_rel(unsigned* p, unsigned v) {
    asm volatile("st.release.gpu.global.u32 [%0], %1;" :: "l"(p), "r"(v) : "memory");
}
__device__ __forceinline__ void ldsm_x4(uint32_t& r0, uint32_t& r1, uint32_t& r2,
                                        uint32_t& r3, uint32_t addr) {
    asm volatile("ldmatrix.sync.aligned.m8n8.x4.shared.b16 {%0,%1,%2,%3}, [%4];"
                 : "=r"(r0), "=r"(r1), "=r"(r2), "=r"(r3) : "r"(addr));
}
__device__ __forceinline__ void ldsm_x4_t(uint32_t& r0, uint32_t& r1, uint32_t& r2,
                                          uint32_t& r3, uint32_t addr) {
    asm volatile("ldmatrix.sync.aligned.m8n8.x4.trans.shared.b16 {%0,%1,%2,%3}, [%4];"
                 : "=r"(r0), "=r"(r1), "=r"(r2), "=r"(r3) : "r"(addr));
}
__device__ __forceinline__ void ldsm_x2_t(uint32_t& r0, uint32_t& r1, uint32_t addr) {
    asm volatile("ldmatrix.sync.aligned.m8n8.x2.trans.shared.b16 {%0,%1}, [%2];"
                 : "=r"(r0), "=r"(r1) : "r"(addr));
}
__device__ __forceinline__ void mma16816(float* d, const uint32_t* a, const uint32_t* b) {
    asm volatile(
        "mma.sync.aligned.m16n8k16.row.col.f32.bf16.bf16.f32 "
        "{%0,%1,%2,%3}, {%4,%5,%6,%7}, {%8,%9}, {%0,%1,%2,%3};"
        : "+f"(d[0]), "+f"(d[1]), "+f"(d[2]), "+f"(d[3])
        : "r"(a[0]), "r"(a[1]), "r"(a[2]), "r"(a[3]), "r"(b[0]), "r"(b[1]));
}

// ---------------------------------------------------------------------------
// weight pre-split (bneck_w, pc_w, hd_w padded to N16)
// ---------------------------------------------------------------------------
__global__ void split_w_kernel(const float* __restrict__ bw, const float* __restrict__ pw,
                               const float* __restrict__ hw)
{
    const int i = blockIdx.x * 256 + threadIdx.x;
    __nv_bfloat16 hi, lo;
    if (i < NHD * NBOT) {
        split2(bw[i], hi, lo);
        g_bwh[i] = hi; g_bwl[i] = lo;
    } else if (i < NHD * NBOT + NBOT * NPC) {
        const int j = i - NHD * NBOT;
        split2(pw[j], hi, lo);
        g_pwh[j] = hi; g_pwl[j] = lo;
    } else if (i < NHD * NBOT + NBOT * NPC + NBOT * 16) {
        const int j = i - NHD * NBOT - NBOT * NPC;
        const int k = j >> 4, n = j & 15;
        split2((n < 12) ? hw[k * 12 + n] : 0.0f, hi, lo);
        g_hdh[j] = hi; g_hdl[j] = lo;
    }
}

// ---------------------------------------------------------------------------
// fp32 GEMM for h0 AND c0 in one launch (blockIdx.z selects); h0 path also
// emits bf16 hi/lo into g_hh/g_hl slot 0.
// ---------------------------------------------------------------------------
__global__ void init_gemm_kernel(const float* __restrict__ A,
                                 const float* __restrict__ W0, const float* __restrict__ b0,
                                 const float* __restrict__ W1, const float* __restrict__ b1,
                                 float* __restrict__ C0, float* __restrict__ C1,
                                 __nv_bfloat16* __restrict__ oh, __nv_bfloat16* __restrict__ ol,
                                 int M, int N, int K)
{
    __shared__ float As[16][68];
    __shared__ float Ws[16][68];
    const int tid = threadIdx.x;
    const int tx = tid & 15, ty = tid >> 4;
    const int n0 = blockIdx.x * 64, m0 = blockIdx.y * 64;
    const int z = blockIdx.z;
    const float* W = z ? W1 : W0;
    const float* bias = z ? b1 : b0;
    float* C = z ? C1 : C0;

    float acc[4][4];
#pragma unroll
    for (int r = 0; r < 4; r++)
#pragma unroll
        for (int q = 0; q < 4; q++) acc[r][q] = 0.0f;

    for (int k0 = 0; k0 < K; k0 += 16) {
        {
            const int k = tid & 15, m = tid >> 4;
#pragma unroll
            for (int p = 0; p < 4; p++) {
                const int mm = m + p * 16;
                float v = 0.0f;
                if (k0 + k < K) v = A[(size_t)(m0 + mm) * K + (k0 + k)];
                As[k][mm] = v;
            }
        }
        {
            const int n = tid & 63, kb = tid >> 6;
#pragma unroll
            for (int p = 0; p < 4; p++) {
                const int kk = kb + p * 4;
                float v = 0.0f;
                if ((k0 + kk < K) && (n0 + n < N)) v = W[(size_t)(k0 + kk) * N + (n0 + n)];
                Ws[kk][n] = v;
            }
        }
        __syncthreads();
#pragma unroll
        for (int kk = 0; kk < 16; kk++) {
            const float4 a4 = *(const float4*)&As[kk][ty * 4];
            const float4 b4 = *(const float4*)&Ws[kk][tx * 4];
            const float av[4] = {a4.x, a4.y, a4.z, a4.w};
            const float bv[4] = {b4.x, b4.y, b4.z, b4.w};
#pragma unroll
            for (int r = 0; r < 4; r++)
#pragma unroll
                for (int q = 0; q < 4; q++)
                    acc[r][q] = fmaf(av[r], bv[q], acc[r][q]);
        }
        __syncthreads();
    }
#pragma unroll
    for (int r = 0; r < 4; r++) {
        const int m = m0 + ty * 4 + r;
#pragma unroll
        for (int q = 0; q < 4; q++) {
            const int n = n0 + tx * 4 + q;
            if (n < N) {
                const float v = acc[r][q] + bias[n];
                C[(size_t)m * N + n] = v;
                if (z == 0) {
                    __nv_bfloat16 hi, lo;
                    split2(v, hi, lo);
                    oh[(size_t)m * N + n] = hi;
                    ol[(size_t)m * N + n] = lo;
                }
            }
        }
    }
}

// ---------------------------------------------------------------------------
// LSTM recurrence + fused bn GEMM — round-14 version verbatim (best: ~510us).
// 128 blocks = 32 row-tiles (32 rows) x 4 unit-groups (32 units = 128 cols).
// ---------------------------------------------------------------------------
#define L_WHH 0u                 // [128][136] bf16
#define L_WHL 34816u
#define L_AHI 69632u             // [32][136] bf16
#define L_ALO 78336u
#define L_BNW_HI 87040u          // [128][72] bf16
#define L_BNW_LO 105472u
#define L_XS  123904u            // [32][4] f32
#define L_WX  124416u            // [3][128] f32
#define L_BS  125952u            // [128] f32
#define L_HST 126464u            // [32][36] f32
#define L_CST 131072u            // [32][36] f32
#define LSTM_SMEM 135680u
#define SWH 136
#define SAH 136
#define SBN 72
#define SHT 36

__global__ void __launch_bounds__(512, 1)
lstm_kernel(const float* __restrict__ x, const float* __restrict__ rnn_w,
            const float* __restrict__ rnn_b,
            float* __restrict__ hs, float* __restrict__ cs,
            float* __restrict__ bn_out)
{
    extern __shared__ __align__(16) char dsm[];
    const uint32_t base_u = smem_u32(dsm);
    __shared__ unsigned s_base;

    const int tid  = threadIdx.x;
    const int wid  = tid >> 5;
    const int lane = tid & 31;
    const int wm   = wid & 1,  wn = wid >> 1;
    const int bwn  = wid >> 1;
    const int g    = lane >> 2, tg = lane & 3;
    const int lr   = lane & 15, lc8 = (lane >> 4) << 3;
    const int cg   = blockIdx.x & 3;
    const int rt   = blockIdx.x >> 2;
    const int hu0  = cg * 32;
    const int r0   = rt * 32;

    float* xs  = (float*)(dsm + L_XS);
    float* wx  = (float*)(dsm + L_WX);
    float* bs  = (float*)(dsm + L_BS);
    float* hst = (float*)(dsm + L_HST);
    float* cst = (float*)(dsm + L_CST);

    for (int i = tid; i < 128 * 128; i += 512) {
        const int k = i >> 7, c = i & 127;
        const int u = c >> 2, q = c & 3;
        __nv_bfloat16 hi, lo;
        split2(rnn_w[(size_t)(3 + k) * NGATE + q * NHD + hu0 + u], hi, lo);
        *(__nv_bfloat16*)(dsm + L_WHH + 2 * (k * SWH + c)) = hi;
        *(__nv_bfloat16*)(dsm + L_WHL + 2 * (k * SWH + c)) = lo;
    }
    for (int i = tid; i < 128 * 8; i += 512) {
        const int k = i >> 3, c4 = i & 7;
        *(uint4*)(dsm + L_BNW_HI + 2 * (k * SBN) + c4 * 16) =
            *(const uint4*)&g_bwh[(size_t)k * NBOT + cg * 64 + c4 * 8];
        *(uint4*)(dsm + L_BNW_LO + 2 * (k * SBN) + c4 * 16) =
            *(const uint4*)&g_bwl[(size_t)k * NBOT + cg * 64 + c4 * 8];
    }
    if (tid < 384) {
        const int m = tid >> 7, c = tid & 127;
        const int u = c >> 2, q = c & 3;
        wx[m * 128 + c] = rnn_w[(size_t)m * NGATE + q * NHD + hu0 + u];
    }
    if (tid < 128) {
        const int u = tid >> 2, q = tid & 3;
        bs[tid] = rnn_b[q * NHD + hu0 + u];
    }
    if (tid == 0) s_base = ld_acq(&g_flag[rt * 4 + cg]);

    const int rA = wm * 16 + g, rB = rA + 8;
    float creg[4];
    if (!(tg & 1)) {
#pragma unroll
        for (int nt = 0; nt < 2; nt++) {
            const int ul = (wn * 16 + nt * 8 + tg * 2) >> 2;
            creg[nt * 2]     = g_c0[(size_t)(r0 + rA) * NHD + hu0 + ul];
            creg[nt * 2 + 1] = g_c0[(size_t)(r0 + rB) * NHD + hu0 + ul];
        }
    }
    __syncthreads();
    const unsigned base = s_base;

    for (int t = 0; t <= TT; t++) {
        if (wid == 0) {
            if (t > 0 && lane < 4 && lane != cg) {
                const unsigned tgt = base + (unsigned)t;
                while (ld_acq(&g_flag[rt * 4 + lane]) < tgt) { }
            }
            __syncwarp();
        }
        __syncthreads();

        {
            const size_t sb = ((size_t)t * BB + r0) * NHD;
            const int row = tid >> 4, ch = tid & 15;
            *(uint4*)(dsm + L_AHI + 2 * (row * SAH + ch * 8)) =
                *(const uint4*)&g_hh[sb + (size_t)row * NHD + ch * 8];
            *(uint4*)(dsm + L_ALO + 2 * (row * SAH + ch * 8)) =
                *(const uint4*)&g_hl[sb + (size_t)row * NHD + ch * 8];
            if (t < TT && tid < 96)
                xs[(tid / 3) * 4 + (tid % 3)] = x[((size_t)t * BB + r0) * 3 + tid];
        }
        __syncthreads();

        float bnacc[4] = {0.0f, 0.0f, 0.0f, 0.0f};

        if (t < TT) {
            float acc[2][4];
#pragma unroll
            for (int a = 0; a < 2; a++)
#pragma unroll
                for (int b = 0; b < 4; b++) acc[a][b] = 0.0f;

#pragma unroll
            for (int kc = 0; kc < 8; kc++) {
                const int k = kc * 16;
                uint32_t ah[4], al[4];
                const uint32_t aoff = 2 * ((wm * 16 + lr) * SAH + k + lc8);
                ldsm_x4(ah[0], ah[1], ah[2], ah[3], base_u + L_AHI + aoff);
                ldsm_x4(al[0], al[1], al[2], al[3], base_u + L_ALO + aoff);
                uint32_t bh[2][2], bl[2][2];
                const uint32_t boff = 2 * ((k + lr) * SWH + wn * 16 + lc8);
                ldsm_x4_t(bh[0][0], bh[0][1], bh[1][0], bh[1][1], base_u + L_WHH + boff);
                ldsm_x4_t(bl[0][0], bl[0][1], bl[1][0], bl[1][1], base_u + L_WHL + boff);
#pragma unroll
                for (int nt = 0; nt < 2; nt++) {
                    mma16816(acc[nt], ah, bh[nt]);
                    mma16816(acc[nt], ah, bl[nt]);
                    mma16816(acc[nt], al, bh[nt]);
                    mma16816(acc[nt], al, bl[nt]);
                }
                uint32_t nbh[2], nbl[2];
                const uint32_t nboff = 2 * ((k + lr) * SBN + bwn * 8);
                ldsm_x2_t(nbh[0], nbh[1], base_u + L_BNW_HI + nboff);
                ldsm_x2_t(nbl[0], nbl[1], base_u + L_BNW_LO + nboff);
                mma16816(bnacc, ah, nbh);
                mma16816(bnacc, ah, nbl);
                mma16816(bnacc, al, nbh);
            }

            const float xa0 = xs[rA * 4], xa1 = xs[rA * 4 + 1], xa2 = xs[rA * 4 + 2];
            const float xb0 = xs[rB * 4], xb1 = xs[rB * 4 + 1], xb2 = xs[rB * 4 + 2];
#pragma unroll
            for (int nt = 0; nt < 2; nt++) {
                const int c0 = wn * 16 + nt * 8 + tg * 2;
#pragma unroll
                for (int cc = 0; cc < 2; cc++) {
                    const int c = c0 + cc;
                    const float w0 = wx[c], w1 = wx[128 + c], w2 = wx[256 + c], bb = bs[c];
                    acc[nt][cc]     += bb + xa0 * w0 + xa1 * w1 + xa2 * w2;
                    acc[nt][2 + cc] += bb + xb0 * w0 + xb1 * w1 + xb2 * w2;
                }
            }

#pragma unroll
            for (int nt = 0; nt < 2; nt++) {
                const float p0 = __shfl_xor_sync(0xffffffffu, acc[nt][0], 1);
                const float p1 = __shfl_xor_sync(0xffffffffu, acc[nt][1], 1);
                const float p2 = __shfl_xor_sync(0xffffffffu, acc[nt][2], 1);
                const float p3 = __shfl_xor_sync(0xffffffffu, acc[nt][3], 1);
                if (!(tg & 1)) {
                    const int ul = (wn * 16 + nt * 8 + tg * 2) >> 2;
                    const float cA = creg[nt * 2] * sigm(p0 + 1.0f)
                                   + sigm(acc[nt][0]) * tanh_fast(acc[nt][1]);
                    const float hA = tanh_fast(cA) * sigm(p1);
                    const float cB = creg[nt * 2 + 1] * sigm(p2 + 1.0f)
                                   + sigm(acc[nt][2]) * tanh_fast(acc[nt][3]);
                    const float hB = tanh_fast(cB) * sigm(p3);
                    creg[nt * 2] = cA;
                    creg[nt * 2 + 1] = cB;
                    hst[rA * SHT + ul] = hA;
                    cst[rA * SHT + ul] = cA;
                    hst[rB * SHT + ul] = hB;
                    cst[rB * SHT + ul] = cB;
                }
            }
            __syncthreads();

            if (tid < 256) {
                const int row = tid >> 3, q4 = tid & 7;
                const float4 hv = *(const float4*)&hst[row * SHT + q4 * 4];
                __nv_bfloat16 h0b, l0b, h1b, l1b, h2b, l2b, h3b, l3b;
                split2(hv.x, h0b, l0b); split2(hv.y, h1b, l1b);
                split2(hv.z, h2b, l2b); split2(hv.w, h3b, l3b);
                const size_t gb = ((size_t)(t + 1) * BB + r0 + row) * NHD + hu0 + q4 * 4;
                __nv_bfloat162 p0; p0.x = h0b; p0.y = h1b;
                __nv_bfloat162 p1; p1.x = h2b; p1.y = h3b;
                __nv_bfloat162 q0; q0.x = l0b; q0.y = l1b;
                __nv_bfloat162 q1; q1.x = l2b; q1.y = l3b;
                *(__nv_bfloat162*)&g_hh[gb]     = p0;
                *(__nv_bfloat162*)&g_hh[gb + 2] = p1;
                *(__nv_bfloat162*)&g_hl[gb]     = q0;
                *(__nv_bfloat162*)&g_hl[gb + 2] = q1;
            }
            __syncthreads();
            if (tid == 0)
                st_rel(&g_flag[rt * 4 + cg], base + (unsigned)t + 1u);

            if (tid < 256) {
                const int row = tid >> 3, q4 = tid & 7;
                const float4 hv = *(const float4*)&hst[row * SHT + q4 * 4];
                const float4 cv = *(const float4*)&cst[row * SHT + q4 * 4];
                const size_t go = ((size_t)t * BB + r0 + row) * NHD + hu0 + q4 * 4;
                *(float4*)&hs[go] = hv;
                *(float4*)&cs[go] = cv;
            }
            if (t >= 1) {
                const size_t row = (size_t)(t - 1) * BB + r0 + wm * 16 + g;
                const int col = cg * 64 + bwn * 8 + tg * 2;
                *(float2*)&bn_out[row * 256 + col] = make_float2(bnacc[0], bnacc[1]);
                *(float2*)&bn_out[(row + 8) * 256 + col] = make_float2(bnacc[2], bnacc[3]);
            }
        } else {
#pragma unroll
            for (int kc = 0; kc < 8; kc++) {
                const int k = kc * 16;
                uint32_t ah[4], al[4];
                const uint32_t aoff = 2 * ((wm * 16 + lr) * SAH + k + lc8);
                ldsm_x4(ah[0], ah[1], ah[2], ah[3], base_u + L_AHI + aoff);
                ldsm_x4(al[0], al[1], al[2], al[3], base_u + L_ALO + aoff);
                uint32_t nbh[2], nbl[2];
                const uint32_t nboff = 2 * ((k + lr) * SBN + bwn * 8);
                ldsm_x2_t(nbh[0], nbh[1], base_u + L_BNW_HI + nboff);
                ldsm_x2_t(nbl[0], nbl[1], base_u + L_BNW_LO + nboff);
                mma16816(bnacc, ah, nbh);
                mma16816(bnacc, ah, nbl);
                mma16816(bnacc, al, nbh);
            }
            const size_t row = (size_t)(TT - 1) * BB + r0 + wm * 16 + g;
            const int col = cg * 64 + bwn * 8 + tg * 2;
            *(float2*)&bn_out[row * 256 + col] = make_float2(bnacc[0], bnacc[1]);
            *(float2*)&bn_out[(row + 8) * 256 + col] = make_float2(bnacc[2], bnacc[3]);
        }
    }
}

// ---------------------------------------------------------------------------
// pc (+hd): 32-row blocks, N=256 via 8 (kc,nq) phases, smem 70656 ->
// 3 CTAs/SM for higher memory-level concurrency. A staged ONCE (both kc).
// ---------------------------------------------------------------------------
#define SA2   264
#define SB2   72
#define PA_HI 0u                 // [32][264] bf16
#define PA_LO 16896u
#define PB_HI 33792u             // [128][72] bf16
#define PB_LO 52224u
#define PC_SMEM 70656u
#define SHD 24

__global__ void __launch_bounds__(256, 3)
pc_kernel(const float* __restrict__ bn, const float* __restrict__ pc_b,
          const float* __restrict__ hd_b,
          float* __restrict__ pc_out, float* __restrict__ hd_out)
{
    extern __shared__ __align__(16) char dsm[];
    const uint32_t base_u = smem_u32(dsm);
    const int tid = threadIdx.x;
    const int wid = tid >> 5, lane = tid & 31;
    const int wm = wid & 1, wn = wid >> 1;    // 2 row-halves(16) x 4 col-grps(16)
    const int g = lane >> 2, tg2 = (lane & 3) * 2;
    const int lr = lane & 15, lc8 = (lane >> 4) << 3;
    const int m0 = blockIdx.x * 32;

    float acc[4][2][4];      // [nq][nt][4]
#pragma unroll
    for (int a = 0; a < 4; a++)
#pragma unroll
        for (int b = 0; b < 2; b++)
#pragma unroll
            for (int c = 0; c < 4; c++) acc[a][b][c] = 0.0f;
    float hacc[2][4];
#pragma unroll
    for (int a = 0; a < 2; a++)
#pragma unroll
        for (int b = 0; b < 4; b++) hacc[a][b] = 0.0f;

    // stage A once: 32 rows x 256 k, bn fp32 -> split bf16 (max MLP)
    for (int i = tid; i < 32 * 128; i += 256) {
        const int row = i >> 7, k2 = (i & 127) * 2;
        const float2 v = *(const float2*)&bn[(size_t)(m0 + row) * 256 + k2];
        __nv_bfloat16 h0b, l0b, h1b, l1b;
        split2(v.x, h0b, l0b); split2(v.y, h1b, l1b);
        __nv_bfloat162 ph; ph.x = h0b; ph.y = h1b;
        __nv_bfloat162 pl; pl.x = l0b; pl.y = l1b;
        *(__nv_bfloat162*)(dsm + PA_HI + 2 * (row * SA2 + k2)) = ph;
        *(__nv_bfloat162*)(dsm + PA_LO + 2 * (row * SA2 + k2)) = pl;
    }

#pragma unroll 1
    for (int kc = 0; kc < 2; kc++) {
#pragma unroll 1
        for (int nq = 0; nq < 4; nq++) {
            __syncthreads();   // B buffer free / A staged on first pass
            for (int i = tid; i < 128 * 8; i += 256) {
                const int row = i >> 3, ch = i & 7;
                *(uint4*)(dsm + PB_HI + 2 * (row * SB2 + ch * 8)) =
                    *(const uint4*)&g_pwh[(size_t)(kc * 128 + row) * NPC + nq * 64 + ch * 8];
                *(uint4*)(dsm + PB_LO + 2 * (row * SB2 + ch * 8)) =
                    *(const uint4*)&g_pwl[(size_t)(kc * 128 + row) * NPC + nq * 64 + ch * 8];
            }
            __syncthreads();

#pragma unroll
            for (int k8 = 0; k8 < 8; k8++) {
                const int k = k8 * 16;
                uint32_t ah[4], al[4];
                const uint32_t aoff = 2 * ((wm * 16 + lr) * SA2 + kc * 128 + k + lc8);
                ldsm_x4(ah[0], ah[1], ah[2], ah[3], base_u + PA_HI + aoff);
                ldsm_x4(al[0], al[1], al[2], al[3], base_u + PA_LO + aoff);
                uint32_t bh[2][2], bl[2][2];
                const uint32_t boff = 2 * ((k + lr) * SB2 + wn * 16 + lc8);
                ldsm_x4_t(bh[0][0], bh[0][1], bh[1][0], bh[1][1], base_u + PB_HI + boff);
                ldsm_x4_t(bl[0][0], bl[0][1], bl[1][0], bl[1][1], base_u + PB_LO + boff);
#pragma unroll
                for (int nt = 0; nt < 2; nt++) {
                    mma16816(acc[nq][nt], ah, bh[nt]);
                    mma16816(acc[nq][nt], ah, bl[nt]);
                    mma16816(acc[nq][nt], al, bh[nt]);
                }
            }
        }

        // hd pass for this kc: overlay B buffer
        __syncthreads();
        for (int i = tid; i < 128 * 16; i += 256) {
            const int row = i >> 4, c = i & 15;
            *(__nv_bfloat16*)(dsm + PB_HI + 2 * (row * SHD + c)) =
                g_hdh[(kc * 128 + row) * 16 + c];
            *(__nv_bfloat16*)(dsm + PB_LO + 2 * (row * SHD + c)) =
                g_hdl[(kc * 128 + row) * 16 + c];
        }
        __syncthreads();

        if (wid < 2) {
#pragma unroll
            for (int k8 = 0; k8 < 8; k8++) {
                const int k = k8 * 16;
                uint32_t ah[4], al[4];
                const uint32_t aoff = 2 * ((wid * 16 + lr) * SA2 + kc * 128 + k + lc8);
                ldsm_x4(ah[0], ah[1], ah[2], ah[3], base_u + PA_HI + aoff);
                ldsm_x4(al[0], al[1], al[2], al[3], base_u + PA_LO + aoff);
                uint32_t bh[2][2], bl[2][2];
                const uint32_t boff = 2 * ((k + lr) * SHD + lc8);
                ldsm_x4_t(bh[0][0], bh[0][1], bh[1][0], bh[1][1], base_u + PB_HI + boff);
                ldsm_x4_t(bl[0][0], bl[0][1], bl[1][0], bl[1][1], base_u + PB_LO + boff);
#pragma unroll
                for (int nt = 0; nt < 2; nt++) {
                    mma16816(hacc[nt], ah, bh[nt]);
                    mma16816(hacc[nt], ah, bl[nt]);
                    mma16816(hacc[nt], al, bh[nt]);
                }
            }
        }
    }

    // epilogue
#pragma unroll
    for (int nq = 0; nq < 4; nq++)
#pragma unroll
    for (int nt = 0; nt < 2; nt++) {
        const int row = m0 + wm * 16 + g;
        const int col = nq * 64 + wn * 16 + nt * 8 + tg2;
        const float b0 = __ldg(&pc_b[col]), b1 = __ldg(&pc_b[col + 1]);
        const float* a4 = acc[nq][nt];
        *(float2*)&pc_out[(size_t)row * 256 + col] = make_float2(a4[0] + b0, a4[1] + b1);
        *(float2*)&pc_out[(size_t)(row + 8) * 256 + col] = make_float2(a4[2] + b0, a4[3] + b1);
    }

    if (wid < 2) {
#pragma unroll
        for (int nt = 0; nt < 2; nt++) {
            const int c0 = nt * 8 + tg2;
            const int rowA = m0 + wid * 16 + g, rowB = rowA + 8;
            if (c0 < 12) {
                const float b = __ldg(&hd_b[c0]);
                hd_out[(size_t)rowA * 12 + c0] = hacc[nt][0] + b;
                hd_out[(size_t)rowB * 12 + c0] = hacc[nt][2] + b;
            }
            if (c0 + 1 < 12) {
                const float b = __ldg(&hd_b[c0 + 1]);
                hd_out[(size_t)rowA * 12 + c0 + 1] = hacc[nt][1] + b;
                hd_out[(size_t)rowB * 12 + c0 + 1] = hacc[nt][3] + b;
            }
        }
    }
}

// ---------------------------------------------------------------------------
extern "C" void kernel_launch(void* const* d_in, const int* in_sizes, int n_in,
                              void* d_out, int out_size)
{
    const float* x       = (const float*)d_in[0];
    const float* init    = (const float*)d_in[1];
    const float* rnn_w   = (const float*)d_in[2];
    const float* rnn_b   = (const float*)d_in[3];
    const float* state_w = (const float*)d_in[4];
    const float* state_b = (const float*)d_in[5];
    const float* cell_w  = (const float*)d_in[6];
    const float* cell_b  = (const float*)d_in[7];
    const float* bneck_w = (const float*)d_in[8];
    const float* pc_w    = (const float*)d_in[9];
    const float* pc_b    = (const float*)d_in[10];
    const float* hd_w    = (const float*)d_in[11];
    const float* hd_b    = (const float*)d_in[12];

    float* out = (float*)d_out;
    float* hd_out = out;
    float* pc_out = hd_out + (size_t)TB * NHDC;
    float* bn_out = pc_out + (size_t)TB * NPC;
    float* hs_out = bn_out + (size_t)TB * NBOT;
    float* cs_out = hs_out + (size_t)TB * NHD;

    float* c0p = nullptr;
    cudaGetSymbolAddress((void**)&c0p, g_c0);
    __nv_bfloat16 *hhp = nullptr, *hlp = nullptr;
    cudaGetSymbolAddress((void**)&hhp, g_hh);
    cudaGetSymbolAddress((void**)&hlp, g_hl);
    float* h0tmp = bn_out;   // scratch; fully overwritten by lstm_kernel's bn

    cudaFuncSetAttribute(lstm_kernel, cudaFuncAttributeMaxDynamicSharedMemorySize, LSTM_SMEM);
    cudaFuncSetAttribute(pc_kernel, cudaFuncAttributeMaxDynamicSharedMemorySize, PC_SMEM);

    init_gemm_kernel<<<dim3(2, 16, 2), 256>>>(init, state_w, state_b, cell_w, cell_b,
                                              h0tmp, c0p, hhp, hlp, BB, NHD, NIC);
    split_w_kernel<<<(NHD * NBOT + NBOT * NPC + NBOT * 16 + 255) / 256, 256>>>(
        bneck_w, pc_w, hd_w);

    lstm_kernel<<<128, 512, LSTM_SMEM>>>(x, rnn_w, rnn_b, hs_out, cs_out, bn_out);

    pc_kernel<<<TB / 32, 256, PC_SMEM>>>(bn_out, pc_b, hd_b, pc_out, hd_out);
}

// round 17
// speedup vs baseline: 1.1683x; 1.1683x over previous
#include <cuda_runtime.h>
#include <cuda_bf16.h>
#include <cstdint>
#include <cstddef>

#define TT   100
#define BB   1024
#define NHD  128
#define NGATE 512
#define NIC  268
#define NBOT 256
#define NPC  256
#define NHDC 12
#define TB   (TT * BB)

// ---------------------------------------------------------------------------
// device scratch
// ---------------------------------------------------------------------------
__device__ float g_c0[BB * NHD];
__device__ __nv_bfloat16 g_hh[(size_t)(TT + 1) * BB * NHD];
__device__ __nv_bfloat16 g_hl[(size_t)(TT + 1) * BB * NHD];
__device__ __nv_bfloat16 g_bwh[NHD * NBOT], g_bwl[NHD * NBOT];
__device__ __nv_bfloat16 g_pwh[NBOT * NPC], g_pwl[NBOT * NPC];
__device__ __nv_bfloat16 g_hdh[NBOT * 16], g_hdl[NBOT * 16];
__device__ unsigned g_flag[32 * 32];

__device__ __forceinline__ float sigm(float v) { return 1.0f / (1.0f + __expf(-v)); }
__device__ __forceinline__ float tanh_fast(float v) {
    return 1.0f - 2.0f / (__expf(2.0f * v) + 1.0f);
}
__device__ __forceinline__ void split2(float v, __nv_bfloat16& hi, __nv_bfloat16& lo) {
    hi = __float2bfloat16(v);
    lo = __float2bfloat16(v - __bfloat162float(hi));
}
__device__ __forceinline__ uint32_t smem_u32(const void* p) {
    uint32_t a;
    asm("{ .reg .u64 t; cvta.to.shared.u64 t, %1; cvt.u32.u64 %0, t; }" : "=r"(a) : "l"(p));
    return a;
}
__device__ __forceinline__ unsigned ld_acq(const unsigned* p) {
    unsigned v;
    asm volatile("ld.acquire.gpu.global.u32 %0, [%1];" : "=r"(v) : "l"(p) : "memory");
    return v;
}
__device__ __forceinline__ void st_rel(unsigned* p, unsigned v) {
    asm volatile("st.release.gpu.global.u32 [%0], %1;" :: "l"(p), "r"(v) : "memory");
}
__device__ __forceinline__ void ldsm_x4(uint32_t& r0, uint32_t& r1, uint32_t& r2,
                                        uint32_t& r3, uint32_t addr) {
    asm volatile("ldmatrix.sync.aligned.m8n8.x4.shared.b16 {%0,%1,%2,%3}, [%4];"
                 : "=r"(r0), "=r"(r1), "=r"(r2), "=r"(r3) : "r"(addr));
}
__device__ __forceinline__ void ldsm_x4_t(uint32_t& r0, uint32_t& r1, uint32_t& r2,
                                          uint32_t& r3, uint32_t addr) {
    asm volatile("ldmatrix.sync.aligned.m8n8.x4.trans.shared.b16 {%0,%1,%2,%3}, [%4];"
                 : "=r"(r0), "=r"(r1), "=r"(r2), "=r"(r3) : "r"(addr));
}
__device__ __forceinline__ void ldsm_x2_t(uint32_t& r0, uint32_t& r1, uint32_t addr) {
    asm volatile("ldmatrix.sync.aligned.m8n8.x2.trans.shared.b16 {%0,%1}, [%2];"
                 : "=r"(r0), "=r"(r1) : "r"(addr));
}
__device__ __forceinline__ void mma16816(float* d, const uint32_t* a, const uint32_t* b) {
    asm volatile(
        "mma.sync.aligned.m16n8k16.row.col.f32.bf16.bf16.f32 "
        "{%0,%1,%2,%3}, {%4,%5,%6,%7}, {%8,%9}, {%0,%1,%2,%3};"
        : "+f"(d[0]), "+f"(d[1]), "+f"(d[2]), "+f"(d[3])
        : "r"(a[0]), "r"(a[1]), "r"(a[2]), "r"(a[3]), "r"(b[0]), "r"(b[1]));
}
#define CP_ASYNC16(dst, src) \
    asm volatile("cp.async.cg.shared.global [%0], [%1], 16;" :: "r"(dst), "l"(src) : "memory")
#define CP_COMMIT() asm volatile("cp.async.commit_group;" ::: "memory")
#define CP_WAIT1()  asm volatile("cp.async.wait_group 1;" ::: "memory")
#define CP_WAIT0()  asm volatile("cp.async.wait_group 0;" ::: "memory")

// ---------------------------------------------------------------------------
// weight pre-split (bneck_w, pc_w, hd_w padded to N16)
// ---------------------------------------------------------------------------
__global__ void split_w_kernel(const float* __restrict__ bw, const float* __restrict__ pw,
                               const float* __restrict__ hw)
{
    const int i = blockIdx.x * 256 + threadIdx.x;
    __nv_bfloat16 hi, lo;
    if (i < NHD * NBOT) {
        split2(bw[i], hi, lo);
        g_bwh[i] = hi; g_bwl[i] = lo;
    } else if (i < NHD * NBOT + NBOT * NPC) {
        const int j = i - NHD * NBOT;
        split2(pw[j], hi, lo);
        g_pwh[j] = hi; g_pwl[j] = lo;
    } else if (i < NHD * NBOT + NBOT * NPC + NBOT * 16) {
        const int j = i - NHD * NBOT - NBOT * NPC;
        const int k = j >> 4, n = j & 15;
        split2((n < 12) ? hw[k * 12 + n] : 0.0f, hi, lo);
        g_hdh[j] = hi; g_hdl[j] = lo;
    }
}

// ---------------------------------------------------------------------------
// fp32 GEMM for h0 AND c0 (blockIdx.z selects); h0 also emits bf16 hi/lo.
// ---------------------------------------------------------------------------
__global__ void init_gemm_kernel(const float* __restrict__ A,
                                 const float* __restrict__ W0, const float* __restrict__ b0,
                                 const float* __restrict__ W1, const float* __restrict__ b1,
                                 float* __restrict__ C0, float* __restrict__ C1,
                                 __nv_bfloat16* __restrict__ oh, __nv_bfloat16* __restrict__ ol,
                                 int M, int N, int K)
{
    __shared__ float As[16][68];
    __shared__ float Ws[16][68];
    const int tid = threadIdx.x;
    const int tx = tid & 15, ty = tid >> 4;
    const int n0 = blockIdx.x * 64, m0 = blockIdx.y * 64;
    const int z = blockIdx.z;
    const float* W = z ? W1 : W0;
    const float* bias = z ? b1 : b0;
    float* C = z ? C1 : C0;

    float acc[4][4];
#pragma unroll
    for (int r = 0; r < 4; r++)
#pragma unroll
        for (int q = 0; q < 4; q++) acc[r][q] = 0.0f;

    for (int k0 = 0; k0 < K; k0 += 16) {
        {
            const int k = tid & 15, m = tid >> 4;
#pragma unroll
            for (int p = 0; p < 4; p++) {
                const int mm = m + p * 16;
                float v = 0.0f;
                if (k0 + k < K) v = A[(size_t)(m0 + mm) * K + (k0 + k)];
                As[k][mm] = v;
            }
        }
        {
            const int n = tid & 63, kb = tid >> 6;
#pragma unroll
            for (int p = 0; p < 4; p++) {
                const int kk = kb + p * 4;
                float v = 0.0f;
                if ((k0 + kk < K) && (n0 + n < N)) v = W[(size_t)(k0 + kk) * N + (n0 + n)];
                Ws[kk][n] = v;
            }
        }
        __syncthreads();
#pragma unroll
        for (int kk = 0; kk < 16; kk++) {
            const float4 a4 = *(const float4*)&As[kk][ty * 4];
            const float4 b4 = *(const float4*)&Ws[kk][tx * 4];
            const float av[4] = {a4.x, a4.y, a4.z, a4.w};
            const float bv[4] = {b4.x, b4.y, b4.z, b4.w};
#pragma unroll
            for (int r = 0; r < 4; r++)
#pragma unroll
                for (int q = 0; q < 4; q++)
                    acc[r][q] = fmaf(av[r], bv[q], acc[r][q]);
        }
        __syncthreads();
    }
#pragma unroll
    for (int r = 0; r < 4; r++) {
        const int m = m0 + ty * 4 + r;
#pragma unroll
        for (int q = 0; q < 4; q++) {
            const int n = n0 + tx * 4 + q;
            if (n < N) {
                const float v = acc[r][q] + bias[n];
                C[(size_t)m * N + n] = v;
                if (z == 0) {
                    __nv_bfloat16 hi, lo;
                    split2(v, hi, lo);
                    oh[(size_t)m * N + n] = hi;
                    ol[(size_t)m * N + n] = lo;
                }
            }
        }
    }
}

// ---------------------------------------------------------------------------
// LSTM recurrence + fused bn GEMM — round-14 version verbatim (~510us).
// 128 blocks = 32 row-tiles (32 rows) x 4 unit-groups (32 units = 128 cols).
// ---------------------------------------------------------------------------
#define L_WHH 0u
#define L_WHL 34816u
#define L_AHI 69632u
#define L_ALO 78336u
#define L_BNW_HI 87040u
#define L_BNW_LO 105472u
#define L_XS  123904u
#define L_WX  124416u
#define L_BS  125952u
#define L_HST 126464u
#define L_CST 131072u
#define LSTM_SMEM 135680u
#define SWH 136
#define SAH 136
#define SBN 72
#define SHT 36

__global__ void __launch_bounds__(512, 1)
lstm_kernel(const float* __restrict__ x, const float* __restrict__ rnn_w,
            const float* __restrict__ rnn_b,
            float* __restrict__ hs, float* __restrict__ cs,
            float* __restrict__ bn_out)
{
    extern __shared__ __align__(16) char dsm[];
    const uint32_t base_u = smem_u32(dsm);
    __shared__ unsigned s_base;

    const int tid  = threadIdx.x;
    const int wid  = tid >> 5;
    const int lane = tid & 31;
    const int wm   = wid & 1,  wn = wid >> 1;
    const int bwn  = wid >> 1;
    const int g    = lane >> 2, tg = lane & 3;
    const int lr   = lane & 15, lc8 = (lane >> 4) << 3;
    const int cg   = blockIdx.x & 3;
    const int rt   = blockIdx.x >> 2;
    const int hu0  = cg * 32;
    const int r0   = rt * 32;

    float* xs  = (float*)(dsm + L_XS);
    float* wx  = (float*)(dsm + L_WX);
    float* bs  = (float*)(dsm + L_BS);
    float* hst = (float*)(dsm + L_HST);
    float* cst = (float*)(dsm + L_CST);

    for (int i = tid; i < 128 * 128; i += 512) {
        const int k = i >> 7, c = i & 127;
        const int u = c >> 2, q = c & 3;
        __nv_bfloat16 hi, lo;
        split2(rnn_w[(size_t)(3 + k) * NGATE + q * NHD + hu0 + u], hi, lo);
        *(__nv_bfloat16*)(dsm + L_WHH + 2 * (k * SWH + c)) = hi;
        *(__nv_bfloat16*)(dsm + L_WHL + 2 * (k * SWH + c)) = lo;
    }
    for (int i = tid; i < 128 * 8; i += 512) {
        const int k = i >> 3, c4 = i & 7;
        *(uint4*)(dsm + L_BNW_HI + 2 * (k * SBN) + c4 * 16) =
            *(const uint4*)&g_bwh[(size_t)k * NBOT + cg * 64 + c4 * 8];
        *(uint4*)(dsm + L_BNW_LO + 2 * (k * SBN) + c4 * 16) =
            *(const uint4*)&g_bwl[(size_t)k * NBOT + cg * 64 + c4 * 8];
    }
    if (tid < 384) {
        const int m = tid >> 7, c = tid & 127;
        const int u = c >> 2, q = c & 3;
        wx[m * 128 + c] = rnn_w[(size_t)m * NGATE + q * NHD + hu0 + u];
    }
    if (tid < 128) {
        const int u = tid >> 2, q = tid & 3;
        bs[tid] = rnn_b[q * NHD + hu0 + u];
    }
    if (tid == 0) s_base = ld_acq(&g_flag[rt * 4 + cg]);

    const int rA = wm * 16 + g, rB = rA + 8;
    float creg[4];
    if (!(tg & 1)) {
#pragma unroll
        for (int nt = 0; nt < 2; nt++) {
            const int ul = (wn * 16 + nt * 8 + tg * 2) >> 2;
            creg[nt * 2]     = g_c0[(size_t)(r0 + rA) * NHD + hu0 + ul];
            creg[nt * 2 + 1] = g_c0[(size_t)(r0 + rB) * NHD + hu0 + ul];
        }
    }
    __syncthreads();
    const unsigned base = s_base;

    for (int t = 0; t <= TT; t++) {
        if (wid == 0) {
            if (t > 0 && lane < 4 && lane != cg) {
                const unsigned tgt = base + (unsigned)t;
                while (ld_acq(&g_flag[rt * 4 + lane]) < tgt) { }
            }
            __syncwarp();
        }
        __syncthreads();

        {
            const size_t sb = ((size_t)t * BB + r0) * NHD;
            const int row = tid >> 4, ch = tid & 15;
            *(uint4*)(dsm + L_AHI + 2 * (row * SAH + ch * 8)) =
                *(const uint4*)&g_hh[sb + (size_t)row * NHD + ch * 8];
            *(uint4*)(dsm + L_ALO + 2 * (row * SAH + ch * 8)) =
                *(const uint4*)&g_hl[sb + (size_t)row * NHD + ch * 8];
            if (t < TT && tid < 96)
                xs[(tid / 3) * 4 + (tid % 3)] = x[((size_t)t * BB + r0) * 3 + tid];
        }
        __syncthreads();

        float bnacc[4] = {0.0f, 0.0f, 0.0f, 0.0f};

        if (t < TT) {
            float acc[2][4];
#pragma unroll
            for (int a = 0; a < 2; a++)
#pragma unroll
                for (int b = 0; b < 4; b++) acc[a][b] = 0.0f;

#pragma unroll
            for (int kc = 0; kc < 8; kc++) {
                const int k = kc * 16;
                uint32_t ah[4], al[4];
                const uint32_t aoff = 2 * ((wm * 16 + lr) * SAH + k + lc8);
                ldsm_x4(ah[0], ah[1], ah[2], ah[3], base_u + L_AHI + aoff);
                ldsm_x4(al[0], al[1], al[2], al[3], base_u + L_ALO + aoff);
                uint32_t bh[2][2], bl[2][2];
                const uint32_t boff = 2 * ((k + lr) * SWH + wn * 16 + lc8);
                ldsm_x4_t(bh[0][0], bh[0][1], bh[1][0], bh[1][1], base_u + L_WHH + boff);
                ldsm_x4_t(bl[0][0], bl[0][1], bl[1][0], bl[1][1], base_u + L_WHL + boff);
#pragma unroll
                for (int nt = 0; nt < 2; nt++) {
                    mma16816(acc[nt], ah, bh[nt]);
                    mma16816(acc[nt], ah, bl[nt]);
                    mma16816(acc[nt], al, bh[nt]);
                    mma16816(acc[nt], al, bl[nt]);
                }
                uint32_t nbh[2], nbl[2];
                const uint32_t nboff = 2 * ((k + lr) * SBN + bwn * 8);
                ldsm_x2_t(nbh[0], nbh[1], base_u + L_BNW_HI + nboff);
                ldsm_x2_t(nbl[0], nbl[1], base_u + L_BNW_LO + nboff);
                mma16816(bnacc, ah, nbh);
                mma16816(bnacc, ah, nbl);
                mma16816(bnacc, al, nbh);
            }

            const float xa0 = xs[rA * 4], xa1 = xs[rA * 4 + 1], xa2 = xs[rA * 4 + 2];
            const float xb0 = xs[rB * 4], xb1 = xs[rB * 4 + 1], xb2 = xs[rB * 4 + 2];
#pragma unroll
            for (int nt = 0; nt < 2; nt++) {
                const int c0 = wn * 16 + nt * 8 + tg * 2;
#pragma unroll
                for (int cc = 0; cc < 2; cc++) {
                    const int c = c0 + cc;
                    const float w0 = wx[c], w1 = wx[128 + c], w2 = wx[256 + c], bb = bs[c];
                    acc[nt][cc]     += bb + xa0 * w0 + xa1 * w1 + xa2 * w2;
                    acc[nt][2 + cc] += bb + xb0 * w0 + xb1 * w1 + xb2 * w2;
                }
            }

#pragma unroll
            for (int nt = 0; nt < 2; nt++) {
                const float p0 = __shfl_xor_sync(0xffffffffu, acc[nt][0], 1);
                const float p1 = __shfl_xor_sync(0xffffffffu, acc[nt][1], 1);
                const float p2 = __shfl_xor_sync(0xffffffffu, acc[nt][2], 1);
                const float p3 = __shfl_xor_sync(0xffffffffu, acc[nt][3], 1);
                if (!(tg & 1)) {
                    const int ul = (wn * 16 + nt * 8 + tg * 2) >> 2;
                    const float cA = creg[nt * 2] * sigm(p0 + 1.0f)
                                   + sigm(acc[nt][0]) * tanh_fast(acc[nt][1]);
                    const float hA = tanh_fast(cA) * sigm(p1);
                    const float cB = creg[nt * 2 + 1] * sigm(p2 + 1.0f)
                                   + sigm(acc[nt][2]) * tanh_fast(acc[nt][3]);
                    const float hB = tanh_fast(cB) * sigm(p3);
                    creg[nt * 2] = cA;
                    creg[nt * 2 + 1] = cB;
                    hst[rA * SHT + ul] = hA;
                    cst[rA * SHT + ul] = cA;
                    hst[rB * SHT + ul] = hB;
                    cst[rB * SHT + ul] = cB;
                }
            }
            __syncthreads();

            if (tid < 256) {
                const int row = tid >> 3, q4 = tid & 7;
                const float4 hv = *(const float4*)&hst[row * SHT + q4 * 4];
                __nv_bfloat16 h0b, l0b, h1b, l1b, h2b, l2b, h3b, l3b;
                split2(hv.x, h0b, l0b); split2(hv.y, h1b, l1b);
                split2(hv.z, h2b, l2b); split2(hv.w, h3b, l3b);
                const size_t gb = ((size_t)(t + 1) * BB + r0 + row) * NHD + hu0 + q4 * 4;
                __nv_bfloat162 p0; p0.x = h0b; p0.y = h1b;
                __nv_bfloat162 p1; p1.x = h2b; p1.y = h3b;
                __nv_bfloat162 q0; q0.x = l0b; q0.y = l1b;
                __nv_bfloat162 q1; q1.x = l2b; q1.y = l3b;
                *(__nv_bfloat162*)&g_hh[gb]     = p0;
                *(__nv_bfloat162*)&g_hh[gb + 2] = p1;
                *(__nv_bfloat162*)&g_hl[gb]     = q0;
                *(__nv_bfloat162*)&g_hl[gb + 2] = q1;
            }
            __syncthreads();
            if (tid == 0)
                st_rel(&g_flag[rt * 4 + cg], base + (unsigned)t + 1u);

            if (tid < 256) {
                const int row = tid >> 3, q4 = tid & 7;
                const float4 hv = *(const float4*)&hst[row * SHT + q4 * 4];
                const float4 cv = *(const float4*)&cst[row * SHT + q4 * 4];
                const size_t go = ((size_t)t * BB + r0 + row) * NHD + hu0 + q4 * 4;
                *(float4*)&hs[go] = hv;
                *(float4*)&cs[go] = cv;
            }
            if (t >= 1) {
                const size_t row = (size_t)(t - 1) * BB + r0 + wm * 16 + g;
                const int col = cg * 64 + bwn * 8 + tg * 2;
                *(float2*)&bn_out[row * 256 + col] = make_float2(bnacc[0], bnacc[1]);
                *(float2*)&bn_out[(row + 8) * 256 + col] = make_float2(bnacc[2], bnacc[3]);
            }
        } else {
#pragma unroll
            for (int kc = 0; kc < 8; kc++) {
                const int k = kc * 16;
                uint32_t ah[4], al[4];
                const uint32_t aoff = 2 * ((wm * 16 + lr) * SAH + k + lc8);
                ldsm_x4(ah[0], ah[1], ah[2], ah[3], base_u + L_AHI + aoff);
                ldsm_x4(al[0], al[1], al[2], al[3], base_u + L_ALO + aoff);
                uint32_t nbh[2], nbl[2];
                const uint32_t nboff = 2 * ((k + lr) * SBN + bwn * 8);
                ldsm_x2_t(nbh[0], nbh[1], base_u + L_BNW_HI + nboff);
                ldsm_x2_t(nbl[0], nbl[1], base_u + L_BNW_LO + nboff);
                mma16816(bnacc, ah, nbh);
                mma16816(bnacc, ah, nbl);
                mma16816(bnacc, al, nbh);
            }
            const size_t row = (size_t)(TT - 1) * BB + r0 + wm * 16 + g;
            const int col = cg * 64 + bwn * 8 + tg * 2;
            *(float2*)&bn_out[row * 256 + col] = make_float2(bnacc[0], bnacc[1]);
            *(float2*)&bn_out[(row + 8) * 256 + col] = make_float2(bnacc[2], bnacc[3]);
        }
    }
}

// ---------------------------------------------------------------------------
// pc (+hd): 64-row blocks, 2 CTAs/SM, cp.async double-buffered B pipeline.
// A staged ONCE [64][264] (both kc). B in 32-k sub-chunks, 2-deep pipeline.
// hd in one pass over resident A. Accumulation order: k ascending (bit-same).
// ---------------------------------------------------------------------------
#define SA2   264
#define PA_HI 0u                  // [64][264] bf16 = 33792B
#define PA_LO 33792u
#define PBH(b) (67584u + (b) * 17408u)   // [32][136] bf16 = 8704B
#define PBL(b) (PBH(b) + 8704u)
#define PH_HI 67584u              // hd overlay: [256][24] bf16 = 12288B
#define PH_LO 79872u
#define PC_SMEM 102400u
#define SB3 136
#define SHD 24

__global__ void __launch_bounds__(256, 2)
pc_kernel(const float* __restrict__ bn, const float* __restrict__ pc_b,
          const float* __restrict__ hd_b,
          float* __restrict__ pc_out, float* __restrict__ hd_out)
{
    extern __shared__ __align__(16) char dsm[];
    const uint32_t base_u = smem_u32(dsm);
    const int tid = threadIdx.x;
    const int wid = tid >> 5, lane = tid & 31;
    const int wm = wid & 1, wn = wid >> 1;   // 2 row-halves(32) x 4 col-grps(32)
    const int g = lane >> 2, tg2 = (lane & 3) * 2;
    const int lr = lane & 15, lc8 = (lane >> 4) << 3;
    const int m0 = blockIdx.x * 64;

    // B sub-chunk stage via cp.async: s in [0,8) covers k rows s*32..+32
    auto issueB = [&](int nh, int s, int b) {
#pragma unroll
        for (int j = tid; j < 512; j += 256) {
            const int row = j >> 4, ch = j & 15;
            const size_t src = (size_t)(s * 32 + row) * NPC + nh * 128 + ch * 8;
            CP_ASYNC16(base_u + PBH(b) + 2 * (row * SB3) + ch * 16,
                       (const char*)&g_pwh[src]);
            CP_ASYNC16(base_u + PBL(b) + 2 * (row * SB3) + ch * 16,
                       (const char*)&g_pwl[src]);
        }
    };

    // prologue: start B(nh=0, s=0) immediately, then stage A under it
    issueB(0, 0, 0);
    CP_COMMIT();

    // stage A once: 64 rows x 256 k, bn fp32 -> split bf16
    for (int i = tid; i < 64 * 128; i += 256) {
        const int row = i >> 7, k2 = (i & 127) * 2;
        const float2 v = *(const float2*)&bn[(size_t)(m0 + row) * 256 + k2];
        __nv_bfloat16 h0b, l0b, h1b, l1b;
        split2(v.x, h0b, l0b); split2(v.y, h1b, l1b);
        __nv_bfloat162 ph; ph.x = h0b; ph.y = h1b;
        __nv_bfloat162 pl; pl.x = l0b; pl.y = l1b;
        *(__nv_bfloat162*)(dsm + PA_HI + 2 * (row * SA2 + k2)) = ph;
        *(__nv_bfloat162*)(dsm + PA_LO + 2 * (row * SA2 + k2)) = pl;
    }

#pragma unroll 1
    for (int nh = 0; nh < 2; nh++) {
        float acc[2][4][4];   // [mt][nt][4]
#pragma unroll
        for (int a = 0; a < 2; a++)
#pragma unroll
            for (int b = 0; b < 4; b++)
#pragma unroll
                for (int c = 0; c < 4; c++) acc[a][b][c] = 0.0f;

#pragma unroll 1
        for (int s = 0; s < 8; s++) {
            const int b = s & 1;
            // issue next sub-chunk (possibly of next nh)
            if (s < 7) { issueB(nh, s + 1, 1 - b); CP_COMMIT(); }
            else if (nh == 0) { issueB(1, 0, 1 - b); CP_COMMIT(); }
            if (s < 7 || nh == 0) CP_WAIT1(); else CP_WAIT0();
            __syncthreads();   // buffer b filled + (s==0,nh==0: A staged)

#pragma unroll
            for (int k8 = 0; k8 < 2; k8++) {
                const int kA = s * 32 + k8 * 16;   // k offset in A
                const int kB = k8 * 16;            // k offset in buffer
                uint32_t ah[2][4], al[2][4];
#pragma unroll
                for (int mt = 0; mt < 2; mt++) {
                    const uint32_t aoff = 2 * ((wm * 32 + mt * 16 + lr) * SA2 + kA + lc8);
                    ldsm_x4(ah[mt][0], ah[mt][1], ah[mt][2], ah[mt][3], base_u + PA_HI + aoff);
                    ldsm_x4(al[mt][0], al[mt][1], al[mt][2], al[mt][3], base_u + PA_LO + aoff);
                }
                uint32_t bh[4][2], bl[4][2];
#pragma unroll
                for (int p = 0; p < 2; p++) {
                    const uint32_t boff = 2 * ((kB + lr) * SB3 + wn * 32 + p * 16 + lc8);
                    ldsm_x4_t(bh[2*p][0], bh[2*p][1], bh[2*p+1][0], bh[2*p+1][1],
                              base_u + PBH(b) + boff);
                    ldsm_x4_t(bl[2*p][0], bl[2*p][1], bl[2*p+1][0], bl[2*p+1][1],
                              base_u + PBL(b) + boff);
                }
#pragma unroll
                for (int mt = 0; mt < 2; mt++)
#pragma unroll
                    for (int nt = 0; nt < 4; nt++) {
                        mma16816(acc[mt][nt], ah[mt], bh[nt]);
                        mma16816(acc[mt][nt], ah[mt], bl[nt]);
                        mma16816(acc[mt][nt], al[mt], bh[nt]);
                    }
            }
            __syncthreads();   // MMA done before buffer b is overwritten
        }

        // epilogue for this nh (register-only reads; no smem hazard)
#pragma unroll
        for (int mt = 0; mt < 2; mt++)
#pragma unroll
        for (int nt = 0; nt < 4; nt++) {
            const int row = m0 + wm * 32 + mt * 16 + g;
            const int col = nh * 128 + wn * 32 + nt * 8 + tg2;
            const float b0 = __ldg(&pc_b[col]), b1 = __ldg(&pc_b[col + 1]);
            const float* a4 = acc[mt][nt];
            *(float2*)&pc_out[(size_t)row * 256 + col] = make_float2(a4[0] + b0, a4[1] + b1);
            *(float2*)&pc_out[(size_t)(row + 8) * 256 + col] =
                make_float2(a4[2] + b0, a4[3] + b1);
        }
    }

    // ---- hd: one pass over resident A, B overlay [256][24] ----
    for (int i = tid; i < 256 * 16; i += 256) {
        const int row = i >> 4, c = i & 15;
        *(__nv_bfloat16*)(dsm + PH_HI + 2 * (row * SHD + c)) = g_hdh[row * 16 + c];
        *(__nv_bfloat16*)(dsm + PH_LO + 2 * (row * SHD + c)) = g_hdl[row * 16 + c];
    }
    __syncthreads();

    if (wid < 4) {
        float hacc[2][4];
#pragma unroll
        for (int a = 0; a < 2; a++)
#pragma unroll
            for (int b = 0; b < 4; b++) hacc[a][b] = 0.0f;

#pragma unroll
        for (int k8 = 0; k8 < 16; k8++) {
            const int k = k8 * 16;
            uint32_t ah[4], al[4];
            const uint32_t aoff = 2 * ((wid * 16 + lr) * SA2 + k + lc8);
            ldsm_x4(ah[0], ah[1], ah[2], ah[3], base_u + PA_HI + aoff);
            ldsm_x4(al[0], al[1], al[2], al[3], base_u + PA_LO + aoff);
            uint32_t bh[2][2], bl[2][2];
            const uint32_t boff = 2 * ((k + lr) * SHD + lc8);
            ldsm_x4_t(bh[0][0], bh[0][1], bh[1][0], bh[1][1], base_u + PH_HI + boff);
            ldsm_x4_t(bl[0][0], bl[0][1], bl[1][0], bl[1][1], base_u + PH_LO + boff);
#pragma unroll
            for (int nt = 0; nt < 2; nt++) {
                mma16816(hacc[nt], ah, bh[nt]);
                mma16816(hacc[nt], ah, bl[nt]);
                mma16816(hacc[nt], al, bh[nt]);
            }
        }
#pragma unroll
        for (int nt = 0; nt < 2; nt++) {
            const int c0 = nt * 8 + tg2;
            const int rowA = m0 + wid * 16 + g, rowB = rowA + 8;
            if (c0 < 12) {
                const float b = __ldg(&hd_b[c0]);
                hd_out[(size_t)rowA * 12 + c0] = hacc[nt][0] + b;
                hd_out[(size_t)rowB * 12 + c0] = hacc[nt][2] + b;
            }
            if (c0 + 1 < 12) {
                const float b = __ldg(&hd_b[c0 + 1]);
                hd_out[(size_t)rowA * 12 + c0 + 1] = hacc[nt][1] + b;
                hd_out[(size_t)rowB * 12 + c0 + 1] = hacc[nt][3] + b;
            }
        }
    }
}

// ---------------------------------------------------------------------------
extern "C" void kernel_launch(void* const* d_in, const int* in_sizes, int n_in,
                              void* d_out, int out_size)
{
    const float* x       = (const float*)d_in[0];
    const float* init    = (const float*)d_in[1];
    const float* rnn_w   = (const float*)d_in[2];
    const float* rnn_b   = (const float*)d_in[3];
    const float* state_w = (const float*)d_in[4];
    const float* state_b = (const float*)d_in[5];
    const float* cell_w  = (const float*)d_in[6];
    const float* cell_b  = (const float*)d_in[7];
    const float* bneck_w = (const float*)d_in[8];
    const float* pc_w    = (const float*)d_in[9];
    const float* pc_b    = (const float*)d_in[10];
    const float* hd_w    = (const float*)d_in[11];
    const float* hd_b    = (const float*)d_in[12];

    float* out = (float*)d_out;
    float* hd_out = out;
    float* pc_out = hd_out + (size_t)TB * NHDC;
    float* bn_out = pc_out + (size_t)TB * NPC;
    float* hs_out = bn_out + (size_t)TB * NBOT;
    float* cs_out = hs_out + (size_t)TB * NHD;

    float* c0p = nullptr;
    cudaGetSymbolAddress((void**)&c0p, g_c0);
    __nv_bfloat16 *hhp = nullptr, *hlp = nullptr;
    cudaGetSymbolAddress((void**)&hhp, g_hh);
    cudaGetSymbolAddress((void**)&hlp, g_hl);
    float* h0tmp = bn_out;   // scratch; fully overwritten by lstm_kernel's bn

    cudaFuncSetAttribute(lstm_kernel, cudaFuncAttributeMaxDynamicSharedMemorySize, LSTM_SMEM);
    cudaFuncSetAttribute(pc_kernel, cudaFuncAttributeMaxDynamicSharedMemorySize, PC_SMEM);

    init_gemm_kernel<<<dim3(2, 16, 2), 256>>>(init, state_w, state_b, cell_w, cell_b,
                                              h0tmp, c0p, hhp, hlp, BB, NHD, NIC);
    split_w_kernel<<<(NHD * NBOT + NBOT * NPC + NBOT * 16 + 255) / 256, 256>>>(
        bneck_w, pc_w, hd_w);

    lstm_kernel<<<128, 512, LSTM_SMEM>>>(x, rnn_w, rnn_b, hs_out, cs_out, bn_out);

    pc_kernel<<<TB / 64, 256, PC_SMEM>>>(bn_out, pc_b, hd_b, pc_out, hd_out);
}